// round 10
// baseline (speedup 1.0000x reference)
#include <cuda_runtime.h>
#include <math.h>

#define BB 2
#define TT 1024
#define DD 128
#define HH 64
#define GRID 128
// DH = 2

// Scratch (allocation-free contract: __device__ globals)
__device__ float g_WT[4][DD * DD];          // transposed Wq, Wk, Wv, Wo
__device__ float g_Qh[BB * HH * TT * 2];    // Q head-major: [(b*64+h)*1024+t] float2
__device__ float g_KV[BB * HH * TT * 4];    // (k0,k1,v0,v1) per (b,h,t)
__device__ float g_AO[BB * TT * DD];        // attention out, row-major [t_glob][d]
__device__ unsigned g_cnt[4];               // global barrier counters (reset at end)

__device__ __forceinline__ float ex2f(float x) {
    float y;
    asm("ex2.approx.ftz.f32 %0, %1;" : "=f"(y) : "f"(x));
    return y;
}

// packed f32x2 helpers (sm_103a — only reachable via PTX)
__device__ __forceinline__ void ffma2(unsigned long long& d,
                                      unsigned long long a,
                                      unsigned long long b) {
    asm("fma.rn.f32x2 %0, %1, %2, %0;" : "+l"(d) : "l"(a), "l"(b));
}
__device__ __forceinline__ unsigned long long mul2(unsigned long long a,
                                                   unsigned long long b) {
    unsigned long long d;
    asm("mul.rn.f32x2 %0, %1, %2;" : "=l"(d) : "l"(a), "l"(b));
    return d;
}
__device__ __forceinline__ void fma2acc(unsigned long long& d,
                                        unsigned long long a,
                                        unsigned long long b,
                                        unsigned long long c) {
    asm("fma.rn.f32x2 %0, %1, %2, %3;" : "=l"(d) : "l"(a), "l"(b), "l"(c));
}
__device__ __forceinline__ void add2(unsigned long long& d, unsigned long long a) {
    asm("add.rn.f32x2 %0, %0, %1;" : "+l"(d) : "l"(a));
}
__device__ __forceinline__ unsigned long long pack2(float v) {
    unsigned long long r;
    asm("mov.b64 %0, {%1, %1};" : "=l"(r) : "f"(v));
    return r;
}
__device__ __forceinline__ unsigned long long packf2(float a, float b) {
    unsigned long long r;
    asm("mov.b64 %0, {%1, %2};" : "=l"(r) : "f"(a), "f"(b));
    return r;
}
__device__ __forceinline__ float2 unpack2(unsigned long long v) {
    float2 f;
    asm("mov.b64 {%0, %1}, %2;" : "=f"(f.x), "=f"(f.y) : "l"(v));
    return f;
}

// Grid-wide barrier. Safe: all GRID blocks are co-resident (128 blocks,
// 1/SM on 148 SMs). Counters monotonically increase within a launch and are
// reset by the last block at kernel end (clean state for every graph replay).
__device__ __forceinline__ void gbar(int i) {
    __syncthreads();
    __threadfence();
    if (threadIdx.x == 0) {
        atomicAdd(&g_cnt[i], 1u);
        while (atomicAdd(&g_cnt[i], 0u) < GRID) { }
        __threadfence();
    }
    __syncthreads();
}

// ---------------------------------------------------------------------------
// One persistent kernel: wtrans -> bar -> qkv -> bar -> attn -> bar -> proj.
// 128 blocks x 512 threads, 48 KB smem (phase-aliased).
// ---------------------------------------------------------------------------
__global__ void __launch_bounds__(512) mega_kernel(const float* __restrict__ x,
                                                   const float* __restrict__ Wq,
                                                   const float* __restrict__ Wk,
                                                   const float* __restrict__ Wv,
                                                   const float* __restrict__ Wo,
                                                   float* __restrict__ out) {
    __shared__ __align__(16) float smem[12288];   // 48 KB

    const int tid = threadIdx.x;
    const int warp = tid >> 5;
    const int lane = tid & 31;
    const int blk = blockIdx.x;

    // ===== Phase 0: weight transpose (blocks 0..63, one 32x32 tile each) =====
    if (blk < 64) {
        float (*t)[33] = reinterpret_cast<float(*)[33]>(smem);
        const int z = blk >> 4;
        const int tl = blk & 15;
        const int row0 = (tl & 3) * 32;
        const int col0 = (tl >> 2) * 32;
        const float* src = (z == 0) ? Wq : (z == 1) ? Wk : (z == 2) ? Wv : Wo;
        float* dst = g_WT[z];
        const int tx = tid & 31, ty = tid >> 5;   // ty 0..15
        #pragma unroll
        for (int i = 0; i < 2; i++)
            t[ty + 16 * i][tx] = src[(row0 + ty + 16 * i) * DD + col0 + tx];
        __syncthreads();
        #pragma unroll
        for (int i = 0; i < 2; i++)
            dst[(col0 + ty + 16 * i) * DD + row0 + tx] = t[tx][ty + 16 * i];
    }
    gbar(0);

    // ===== Phase 1: QKV projection. Block owns 32 rows x 64 cols, 3 z's =====
    {
        float (*sX)[DD] = reinterpret_cast<float(*)[DD]>(smem);          // 16 KB
        float (*sW)[64] = reinterpret_cast<float(*)[64]>(smem + 4096);   // 32 KB

        const int row0 = (blk & 63) * 32;
        const int col0 = (blk >> 6) * 64;

        // Stage 32 x-rows once (1024 float4, 2/thread)
        #pragma unroll
        for (int i = 0; i < 2; i++) {
            const int idx = tid + i * 512;
            reinterpret_cast<float4*>(&sX[0][0])[idx] =
                reinterpret_cast<const float4*>(x + row0 * DD)[idx];
        }

        for (int z = 0; z < 3; z++) {
            __syncthreads();   // prior compute done reading sW (and sX visible)
            #pragma unroll
            for (int i = 0; i < 4; i++) {
                const int idx = tid + i * 512;
                const int k = idx >> 4;
                const int c4 = (idx & 15) * 4;
                *reinterpret_cast<float4*>(&sW[k][c4]) =
                    *reinterpret_cast<const float4*>(g_WT[z] + k * DD + col0 + c4);
            }
            __syncthreads();

            if (warp < 8) {
                const int r0 = warp * 4;
                const int c2 = lane * 2;
                unsigned long long acc[4] = {0ull, 0ull, 0ull, 0ull};
                #pragma unroll 8
                for (int k = 0; k < DD; k++) {
                    const unsigned long long wv =
                        *reinterpret_cast<const unsigned long long*>(&sW[k][c2]);
                    ffma2(acc[0], pack2(sX[r0 + 0][k]), wv);
                    ffma2(acc[1], pack2(sX[r0 + 1][k]), wv);
                    ffma2(acc[2], pack2(sX[r0 + 2][k]), wv);
                    ffma2(acc[3], pack2(sX[r0 + 3][k]), wv);
                }
                const int h = (col0 >> 1) + lane;   // lane's col pair = head h
                float2* __restrict__ Qp  = reinterpret_cast<float2*>(g_Qh);
                float2* __restrict__ KVp = reinterpret_cast<float2*>(g_KV);
                #pragma unroll
                for (int i = 0; i < 4; i++) {
                    const int rg = row0 + r0 + i;
                    const int b = rg >> 10;
                    const int t0 = rg & 1023;
                    const int idx = (b * HH + h) * TT + t0;
                    const float2 f = unpack2(acc[i]);
                    if (z == 0)      Qp[idx] = f;
                    else if (z == 1) KVp[idx * 2] = f;        // K -> .xy
                    else             KVp[idx * 2 + 1] = f;    // V -> .zw
                }
            }
        }
    }
    gbar(1);

    // ===== Phase 2: causal attention. Block = (b,h). Round-9 f32x2 loop =====
    {
        float4* sKp = reinterpret_cast<float4*>(smem);         // 8 KB
        float4* sVp = reinterpret_cast<float4*>(smem) + 512;   // 8 KB

        const int b = blk >> 6;
        const int h = blk & 63;

        const float4* __restrict__ KVp = reinterpret_cast<const float4*>(g_KV) + blk * TT;
        const float2* __restrict__ Qp  = reinterpret_cast<const float2*>(g_Qh) + blk * TT;

        // Pair-major staging: thread handles key pair (2*tid, 2*tid+1)
        {
            const float4 a = KVp[2 * tid];
            const float4 c = KVp[2 * tid + 1];
            sKp[tid] = make_float4(a.x, c.x, a.y, c.y);
            sVp[tid] = make_float4(a.z, c.z, a.w, c.w);
        }
        __syncthreads();

        // fold 1/(sqrt(DH)*temperature) and log2(e) into the query
        const float cf = 1.4426950408889634f / (1.4142135623730951f * 0.8f);
        float2* __restrict__ Op = reinterpret_cast<float2*>(g_AO);

        #pragma unroll
        for (int qi = 0; qi < 2; qi++) {
            const int q = qi ? (TT - 1 - tid) : tid;
            const float2 qv = Qp[q];
            const float q0 = qv.x * cf;
            const float q1 = qv.y * cf;
            const unsigned long long q0p = pack2(q0);
            const unsigned long long q1p = pack2(q1);

            const int npairs = (q + 1) >> 1;
            unsigned long long lp = 0ull, o0p = 0ull, o1p = 0ull;

            #pragma unroll 2
            for (int m = 0; m < npairs; m++) {
                const ulonglong2 kk = *reinterpret_cast<const ulonglong2*>(&sKp[m]);
                unsigned long long s01;
                fma2acc(s01, q1p, kk.y, mul2(q0p, kk.x));
                const float2 s = unpack2(s01);
                const unsigned long long p01 = packf2(ex2f(s.x), ex2f(s.y));
                const ulonglong2 vv = *reinterpret_cast<const ulonglong2*>(&sVp[m]);
                add2(lp, p01);
                ffma2(o0p, p01, vv.x);
                ffma2(o1p, p01, vv.y);
            }

            const float2 lf = unpack2(lp);
            const float2 o0f = unpack2(o0p);
            const float2 o1f = unpack2(o1p);
            float l = lf.x + lf.y;
            float o0 = o0f.x + o0f.y;
            float o1 = o1f.x + o1f.y;

            if (((q + 1) & 1) != 0) {            // q even: scalar tail for key q
                const float4 kk = sKp[q >> 1];
                const float4 vv = sVp[q >> 1];
                const float s = fmaf(q1, kk.z, q0 * kk.x);
                const float p = ex2f(s);
                l += p;
                o0 = fmaf(p, vv.x, o0);
                o1 = fmaf(p, vv.z, o1);
            }

            const float inv = 1.0f / l;
            Op[(b * TT + q) * HH + h] = make_float2(o0 * inv, o1 * inv);
        }
    }
    gbar(2);

    // ===== Phase 3: output projection. Block owns 32 rows x 64 cols =====
    {
        float (*sX)[DD] = reinterpret_cast<float(*)[DD]>(smem);
        float (*sW)[64] = reinterpret_cast<float(*)[64]>(smem + 4096);

        const int row0 = (blk & 63) * 32;
        const int col0 = (blk >> 6) * 64;

        #pragma unroll
        for (int i = 0; i < 2; i++) {
            const int idx = tid + i * 512;
            reinterpret_cast<float4*>(&sX[0][0])[idx] =
                reinterpret_cast<const float4*>(g_AO + row0 * DD)[idx];
        }
        #pragma unroll
        for (int i = 0; i < 4; i++) {
            const int idx = tid + i * 512;
            const int k = idx >> 4;
            const int c4 = (idx & 15) * 4;
            *reinterpret_cast<float4*>(&sW[k][c4]) =
                *reinterpret_cast<const float4*>(g_WT[3] + k * DD + col0 + c4);
        }
        __syncthreads();

        if (warp < 8) {
            const int r0 = warp * 4;
            const int c2 = lane * 2;
            unsigned long long acc[4] = {0ull, 0ull, 0ull, 0ull};
            #pragma unroll 8
            for (int k = 0; k < DD; k++) {
                const unsigned long long wv =
                    *reinterpret_cast<const unsigned long long*>(&sW[k][c2]);
                ffma2(acc[0], pack2(sX[r0 + 0][k]), wv);
                ffma2(acc[1], pack2(sX[r0 + 1][k]), wv);
                ffma2(acc[2], pack2(sX[r0 + 2][k]), wv);
                ffma2(acc[3], pack2(sX[r0 + 3][k]), wv);
            }
            #pragma unroll
            for (int i = 0; i < 4; i++) {
                const int rg = row0 + r0 + i;
                const float2 f = unpack2(acc[i]);
                *reinterpret_cast<float2*>(out + rg * DD + col0 + c2) = f;
            }
        }
    }

    // ===== Epilogue: last block resets barrier counters for next replay =====
    __threadfence();
    __syncthreads();
    if (tid == 0) {
        const unsigned prev = atomicAdd(&g_cnt[3], 1u);
        if (prev == GRID - 1) {
            atomicExch(&g_cnt[0], 0u);
            atomicExch(&g_cnt[1], 0u);
            atomicExch(&g_cnt[2], 0u);
            atomicExch(&g_cnt[3], 0u);
        }
    }
}

extern "C" void kernel_launch(void* const* d_in, const int* in_sizes, int n_in,
                              void* d_out, int out_size) {
    const float* x  = (const float*)d_in[0];
    const float* Wq = (const float*)d_in[1];
    const float* Wk = (const float*)d_in[2];
    const float* Wv = (const float*)d_in[3];
    const float* Wo = (const float*)d_in[4];
    float* out = (float*)d_out;

    mega_kernel<<<GRID, 512>>>(x, Wq, Wk, Wv, Wo, out);
}